// round 10
// baseline (speedup 1.0000x reference)
#include <cuda_runtime.h>
#include <mma.h>
#include <math.h>
#include <stdint.h>

using namespace nvcuda;

#define Bn 4
#define Tn 2048
#define Dn 1024
#define Hn 16
#define HDn 64
#define MROWS (Bn*Tn)      // 8192
#define QKVN (3*Dn)        // 3072

__device__ float g_qkv[(size_t)MROWS * QKVN];
__device__ float g_attn[(size_t)MROWS * Dn];
__device__ float g_xr[(size_t)MROWS * Dn];
__device__ float g_wq[(size_t)Dn * QKVN];
__device__ float g_wo[(size_t)Dn * Dn];

__device__ __forceinline__ float to_tf32(float x) {
    uint32_t u;
    asm("cvt.rna.tf32.f32 %0, %1;" : "=r"(u) : "f"(x));
    return __uint_as_float(u);
}
__device__ __forceinline__ uint32_t s2u(const void* p) {
    return (uint32_t)__cvta_generic_to_shared(p);
}
__device__ __forceinline__ void cp16(uint32_t dst, const void* src) {
    asm volatile("cp.async.cg.shared.global [%0], [%1], 16;" :: "r"(dst), "l"(src));
}
__device__ __forceinline__ void cp_commit() { asm volatile("cp.async.commit_group;"); }
__device__ __forceinline__ void cp_wait0()  { asm volatile("cp.async.wait_group 0;"); }

__global__ void __launch_bounds__(256) preround_kernel(
    const float* __restrict__ src, float* __restrict__ dst, int total4)
{
    int idx = blockIdx.x * blockDim.x + threadIdx.x;
    if (idx >= total4) return;
    float4 v = *(const float4*)&src[idx * 4];
    v.x = to_tf32(v.x); v.y = to_tf32(v.y);
    v.z = to_tf32(v.z); v.w = to_tf32(v.w);
    *(float4*)&dst[idx * 4] = v;
}

// ---------------------------------------------------------------------------
// TF32 GEMM v4: block tile 64x128, warp tile 32x32 (2x2 frags, 32 acc regs),
// 8 warps, BK=32, cp.async double buffer. Small warp tile => low regs =>
// 4 blocks/SM => 32 warps/SM for latency hiding.
// ---------------------------------------------------------------------------
#define AP_A 36
#define AP_B 132
#define A_STG (64*AP_A)
#define B_STG (32*AP_B)
#define GEMM_SMEM ((2*A_STG + 2*B_STG) * 4)

template <int ROUND_OUT>
__global__ void __launch_bounds__(256, 4) gemm_tf32_v4(
    const float* __restrict__ A, const float* __restrict__ Bm,
    float* __restrict__ C, int M, int N, int K)
{
    extern __shared__ float sm[];
    float* As = sm;                     // [2][64][AP_A]
    float* Bs = sm + 2*A_STG;           // [2][32][AP_B]

    const int tid = threadIdx.x;
    const int bm = blockIdx.y * 64;
    const int bn = blockIdx.x * 128;
    const int w  = tid >> 5;
    const int wm = (w >> 2) * 32;       // 0 or 32
    const int wn = (w & 3) * 32;        // 0,32,64,96

    wmma::fragment<wmma::accumulator, 16, 16, 8, float> acc[2][2];
    #pragma unroll
    for (int i = 0; i < 2; i++)
        #pragma unroll
        for (int j = 0; j < 2; j++) wmma::fill_fragment(acc[i][j], 0.f);

    const int nk = K / 32;

    auto prefetch = [&](int kt, int stg) {
        const int k0 = kt * 32;
        float* ad = As + stg * A_STG;
        float* bd = Bs + stg * B_STG;
        #pragma unroll
        for (int i = 0; i < 2; i++) {           // A: 64x32 = 512 float4
            int id = tid + 256*i;
            int r = id >> 3, c = (id & 7) * 4;
            cp16(s2u(ad + r*AP_A + c), &A[(size_t)(bm + r) * K + k0 + c]);
        }
        #pragma unroll
        for (int i = 0; i < 4; i++) {           // B: 32x128 = 1024 float4
            int id = tid + 256*i;
            int r = id >> 5, c = (id & 31) * 4;
            cp16(s2u(bd + r*AP_B + c), &Bm[(size_t)(k0 + r) * N + bn + c]);
        }
        cp_commit();
    };

    prefetch(0, 0);
    int stg = 0;

    for (int kt = 0; kt < nk; kt++) {
        cp_wait0();
        __syncthreads();
        if (kt + 1 < nk) prefetch(kt + 1, stg ^ 1);

        const float* a0 = As + stg * A_STG;
        const float* b0 = Bs + stg * B_STG;
        #pragma unroll
        for (int kk = 0; kk < 4; kk++) {
            wmma::fragment<wmma::matrix_a, 16, 16, 8, wmma::precision::tf32, wmma::row_major> af[2];
            wmma::fragment<wmma::matrix_b, 16, 16, 8, wmma::precision::tf32, wmma::row_major> bf[2];
            #pragma unroll
            for (int i = 0; i < 2; i++)
                wmma::load_matrix_sync(af[i], a0 + (wm + i*16)*AP_A + kk*8, AP_A);
            #pragma unroll
            for (int j = 0; j < 2; j++)
                wmma::load_matrix_sync(bf[j], b0 + (kk*8)*AP_B + wn + j*16, AP_B);
            #pragma unroll
            for (int i = 0; i < 2; i++)
                #pragma unroll
                for (int j = 0; j < 2; j++)
                    wmma::mma_sync(acc[i][j], af[i], bf[j], acc[i][j]);
        }
        stg ^= 1;
    }

    #pragma unroll
    for (int i = 0; i < 2; i++)
        #pragma unroll
        for (int j = 0; j < 2; j++) {
            if (ROUND_OUT) {
                #pragma unroll
                for (int t = 0; t < acc[i][j].num_elements; t++)
                    acc[i][j].x[t] = to_tf32(acc[i][j].x[t]);
            }
            wmma::store_matrix_sync(&C[(size_t)(bm + wm + i*16) * N + bn + wn + j*16],
                                    acc[i][j], N, wmma::mem_row_major);
        }
}

__global__ void __launch_bounds__(256) bias_add_kernel(
    float* __restrict__ out, const float* __restrict__ bias, int total4, int N)
{
    int idx = blockIdx.x * blockDim.x + threadIdx.x;
    if (idx >= total4) return;
    int col = (idx * 4) & (N - 1);
    float4 v = *(float4*)&out[idx * 4];
    v.x += bias[col+0]; v.y += bias[col+1];
    v.z += bias[col+2]; v.w += bias[col+3];
    *(float4*)&out[idx * 4] = v;
}

// ---------------------------------------------------------------------------
// RoPE + L2 norm, writes tf32-rounded q,k in place.
// ---------------------------------------------------------------------------
__global__ void __launch_bounds__(256) rope_norm_kernel(float* __restrict__ qkv)
{
    const int gw = (blockIdx.x * blockDim.x + threadIdx.x) >> 5;
    const int lane = threadIdx.x & 31;
    const int which = gw & 1;
    const int h = (gw >> 1) & (Hn - 1);
    const int t = (gw >> 5) & (Tn - 1);
    const int b = gw >> 16;

    float* p = qkv + (size_t)(b*Tn + t) * QKVN + which*Dn + h*HDn;

    const float inv_freq = exp2f(-(float)lane * (13.287712379549449f / 32.f));
    const float ang = (float)t * inv_freq;
    float s, c;
    sincosf(ang, &s, &c);

    const float x1 = p[lane];
    const float x2 = p[lane + 32];
    const float r1 = x1*c - x2*s;
    const float r2 = x1*s + x2*c;

    float ss = r1*r1 + r2*r2;
    #pragma unroll
    for (int off = 16; off; off >>= 1)
        ss += __shfl_xor_sync(0xffffffffu, ss, off);

    const float inv = rsqrtf(ss + 1e-6f);
    p[lane]      = to_tf32(r1 * inv);
    p[lane + 32] = to_tf32(r2 * inv);
}

// ---------------------------------------------------------------------------
// TF32 flash attention (R6-best config, AP=68): 64 q-rows / 128 threads /
// 4 warps, cp.async double-buffered K/V, exp without max/rescale.
// ---------------------------------------------------------------------------
#define AP 68
#define KV_STG (64*AP)
#define ATT_SMEM ((64*AP + 2*KV_STG + 2*KV_STG + 64*AP + 64) * 4)

__global__ void __launch_bounds__(128) attn_tc_kernel(
    const float* __restrict__ qkv, float* __restrict__ outp)
{
    extern __shared__ float sm[];
    float* Qs   = sm;
    float* Ks   = Qs + 64*AP;
    float* Vs   = Ks + 2*KV_STG;
    float* Ps   = Vs + 2*KV_STG;
    float* lrow = Ps + 64*AP;

    const int tid  = threadIdx.x;
    const int w    = tid >> 5;
    const int lane = tid & 31;

    const int qt = blockIdx.x & 31;
    const int h  = (blockIdx.x >> 5) & (Hn-1);
    const int b  = blockIdx.x >> 9;
    const int q0 = qt * 64;

    const float* qbase = qkv + (size_t)(b*Tn) * QKVN + h*HDn;
    const float* kbase = qbase + Dn;
    const float* vbase = qbase + 2*Dn;

    auto prefetch_kv = [&](int kt, int stg) {
        float* kd = Ks + stg*KV_STG;
        float* vd = Vs + stg*KV_STG;
        #pragma unroll
        for (int i = 0; i < 8; i++) {
            int id = tid + 128*i;
            int r = id >> 4, c = (id & 15) * 4;
            cp16(s2u(kd + r*AP + c), kbase + (size_t)(kt*64 + r) * QKVN + c);
        }
        #pragma unroll
        for (int i = 0; i < 8; i++) {
            int id = tid + 128*i;
            int r = id >> 4, c = (id & 15) * 4;
            cp16(s2u(vd + r*AP + c), vbase + (size_t)(kt*64 + r) * QKVN + c);
        }
        cp_commit();
    };

    prefetch_kv(0, 0);

    {
        const int r  = tid >> 1;
        const int c0 = (tid & 1) * 32;
        const float* src = qbase + (size_t)(q0 + r) * QKVN + c0;
        float* dst = Qs + r*AP + c0;
        #pragma unroll
        for (int j = 0; j < 8; j++) {
            float4 v = *(const float4*)(src + j*4);
            dst[j*4+0] = 0.125f * v.x;
            dst[j*4+1] = 0.125f * v.y;
            dst[j*4+2] = 0.125f * v.z;
            dst[j*4+3] = 0.125f * v.w;
        }
    }
    if (tid < 64) lrow[tid] = 0.f;

    wmma::fragment<wmma::accumulator, 16, 16, 8, float> oacc[4];
    #pragma unroll
    for (int j = 0; j < 4; j++) wmma::fill_fragment(oacc[j], 0.f);

    const int rowm = w * 16;
    int stg = 0;

    for (int kt = 0; kt < Tn/64; kt++) {
        cp_wait0();
        __syncthreads();
        if (kt + 1 < Tn/64) prefetch_kv(kt + 1, stg ^ 1);

        const float* kc = Ks + stg*KV_STG;
        const float* vc = Vs + stg*KV_STG;

        wmma::fragment<wmma::accumulator, 16, 16, 8, float> sacc[4];
        #pragma unroll
        for (int j = 0; j < 4; j++) wmma::fill_fragment(sacc[j], 0.f);
        #pragma unroll
        for (int ks = 0; ks < 8; ks++) {
            wmma::fragment<wmma::matrix_a, 16, 16, 8, wmma::precision::tf32, wmma::row_major> aq;
            wmma::load_matrix_sync(aq, Qs + rowm*AP + ks*8, AP);
            #pragma unroll
            for (int j = 0; j < 4; j++) {
                wmma::fragment<wmma::matrix_b, 16, 16, 8, wmma::precision::tf32, wmma::col_major> bk;
                wmma::load_matrix_sync(bk, kc + j*16*AP + ks*8, AP);
                wmma::mma_sync(sacc[j], aq, bk, sacc[j]);
            }
        }
        #pragma unroll
        for (int j = 0; j < 4; j++)
            wmma::store_matrix_sync(Ps + rowm*AP + j*16, sacc[j], AP, wmma::mem_row_major);
        __syncwarp();

        {
            const int rr = rowm + (lane >> 1);
            const int cc = (lane & 1) * 32;
            float* pr = Ps + rr*AP + cc;
            float sum = 0.f;
            #pragma unroll
            for (int j = 0; j < 32; j++) {
                float e = __expf(pr[j]);
                sum += e;
                pr[j] = to_tf32(e);
            }
            sum += __shfl_xor_sync(0xffffffffu, sum, 1);
            if (!(lane & 1)) lrow[rr] += sum;
        }
        __syncwarp();

        #pragma unroll
        for (int ks = 0; ks < 8; ks++) {
            wmma::fragment<wmma::matrix_a, 16, 16, 8, wmma::precision::tf32, wmma::row_major> ap;
            wmma::load_matrix_sync(ap, Ps + rowm*AP + ks*8, AP);
            #pragma unroll
            for (int j = 0; j < 4; j++) {
                wmma::fragment<wmma::matrix_b, 16, 16, 8, wmma::precision::tf32, wmma::row_major> bv;
                wmma::load_matrix_sync(bv, vc + ks*8*AP + j*16, AP);
                wmma::mma_sync(oacc[j], ap, bv, oacc[j]);
            }
        }
        stg ^= 1;
    }

    __syncthreads();
    #pragma unroll
    for (int j = 0; j < 4; j++)
        wmma::store_matrix_sync(Ps + rowm*AP + j*16, oacc[j], AP, wmma::mem_row_major);
    __syncthreads();

    {
        const int r  = tid >> 1;
        const int c0 = (tid & 1) * 32;
        const float inv = 1.f / lrow[r];
        const float* srcr = Ps + r*AP + c0;
        float* dst = outp + (size_t)(b*Tn + q0 + r) * Dn + h*HDn + c0;
        #pragma unroll
        for (int j = 0; j < 8; j++) {
            float4 v;
            v.x = to_tf32(srcr[j*4+0] * inv);
            v.y = to_tf32(srcr[j*4+1] * inv);
            v.z = to_tf32(srcr[j*4+2] * inv);
            v.w = to_tf32(srcr[j*4+3] * inv);
            *(float4*)(dst + j*4) = v;
        }
    }
}

// ---------------------------------------------------------------------------
extern "C" void kernel_launch(void* const* d_in, const int* in_sizes, int n_in,
                              void* d_out, int out_size)
{
    const float* x    = (const float*)d_in[0];
    const float* Wqkv = (const float*)d_in[1];
    const float* Wo   = (const float*)d_in[2];
    const float* bo   = (const float*)d_in[3];
    float* out = (float*)d_out;

    float *qkv, *att, *xr, *wq, *wo;
    cudaGetSymbolAddress((void**)&qkv, g_qkv);
    cudaGetSymbolAddress((void**)&att, g_attn);
    cudaGetSymbolAddress((void**)&xr,  g_xr);
    cudaGetSymbolAddress((void**)&wq,  g_wq);
    cudaGetSymbolAddress((void**)&wo,  g_wo);

    cudaFuncSetAttribute(gemm_tf32_v4<0>,
                         cudaFuncAttributeMaxDynamicSharedMemorySize, GEMM_SMEM);
    cudaFuncSetAttribute(gemm_tf32_v4<1>,
                         cudaFuncAttributeMaxDynamicSharedMemorySize, GEMM_SMEM);
    cudaFuncSetAttribute(attn_tc_kernel,
                         cudaFuncAttributeMaxDynamicSharedMemorySize, ATT_SMEM);

    // 0) pre-round inputs to tf32
    {
        int n4;
        n4 = MROWS*Dn/4;   preround_kernel<<<(n4+255)/256, 256>>>(x,    xr, n4);
        n4 = Dn*QKVN/4;    preround_kernel<<<(n4+255)/256, 256>>>(Wqkv, wq, n4);
        n4 = Dn*Dn/4;      preround_kernel<<<(n4+255)/256, 256>>>(Wo,   wo, n4);
    }
    // 1) qkv = xr @ wq  (epilogue rounds to tf32)
    {
        dim3 grid(QKVN/128, MROWS/64);    // (24, 128)
        gemm_tf32_v4<1><<<grid, 256, GEMM_SMEM>>>(xr, wq, qkv, MROWS, QKVN, Dn);
    }
    // 2) RoPE + L2 norm (writes tf32)
    {
        int warps = Bn*Tn*Hn*2;
        rope_norm_kernel<<<warps/8, 256>>>(qkv);
    }
    // 3) attention (writes tf32)
    {
        dim3 grid(Bn * Hn * (Tn/64));   // 2048
        attn_tc_kernel<<<grid, 128, ATT_SMEM>>>(qkv, att);
    }
    // 4) out = att @ wo + bo
    {
        dim3 grid(Dn/128, MROWS/64);      // (8, 128)
        gemm_tf32_v4<0><<<grid, 256, GEMM_SMEM>>>(att, wo, out, MROWS, Dn, Dn);
        int total4 = MROWS * Dn / 4;
        bias_add_kernel<<<(total4 + 255)/256, 256>>>(out, bo, total4, Dn);
    }
}

// round 11
// speedup vs baseline: 3.2097x; 3.2097x over previous
#include <cuda_runtime.h>
#include <cuda_fp16.h>
#include <mma.h>
#include <math.h>
#include <stdint.h>

using namespace nvcuda;

#define Bn 4
#define Tn 2048
#define Dn 1024
#define Hn 16
#define HDn 64
#define MROWS (Bn*Tn)      // 8192
#define QKVN (3*Dn)        // 3072

__device__ float  g_qkv[(size_t)MROWS * QKVN];    // GEMM1 output (fp32)
__device__ __half g_qkvh[(size_t)MROWS * QKVN];   // fp16 q(prescaled),k,v for attention
__device__ __half g_atth[(size_t)MROWS * Dn];     // attention output (fp16)
__device__ __half g_xh[(size_t)MROWS * Dn];
__device__ __half g_wqh[(size_t)Dn * QKVN];
__device__ __half g_woh[(size_t)Dn * Dn];

__device__ __forceinline__ uint32_t s2u(const void* p) {
    return (uint32_t)__cvta_generic_to_shared(p);
}
__device__ __forceinline__ void cp16(uint32_t dst, const void* src) {
    asm volatile("cp.async.cg.shared.global [%0], [%1], 16;" :: "r"(dst), "l"(src));
}
__device__ __forceinline__ void cp_commit() { asm volatile("cp.async.commit_group;"); }
__device__ __forceinline__ void cp_wait0()  { asm volatile("cp.async.wait_group 0;"); }

// float -> half conversion, 4 elems/thread
__global__ void __launch_bounds__(256) f2h_kernel(
    const float* __restrict__ src, __half* __restrict__ dst, int total4)
{
    int idx = blockIdx.x * blockDim.x + threadIdx.x;
    if (idx >= total4) return;
    float4 v = *(const float4*)&src[idx * 4];
    __half2 h0 = __floats2half2_rn(v.x, v.y);
    __half2 h1 = __floats2half2_rn(v.z, v.w);
    *(__half2*)&dst[idx*4]   = h0;
    *(__half2*)&dst[idx*4+2] = h1;
}

// Convert v columns of qkv (fp32) into g_qkvh (fp16), strided.
__global__ void __launch_bounds__(256) vconv_kernel(
    const float* __restrict__ qkv, __half* __restrict__ qkvh)
{
    int idx = blockIdx.x * blockDim.x + threadIdx.x;   // total MROWS*Dn/4
    if (idx >= MROWS*Dn/4) return;
    int row = idx >> 8;                 // Dn/4 = 256 chunks per row
    int col = (idx & 255) * 4;
    const float* s = qkv + (size_t)row * QKVN + 2*Dn + col;
    __half* d = qkvh + (size_t)row * QKVN + 2*Dn + col;
    float4 v = *(const float4*)s;
    *(__half2*)d     = __floats2half2_rn(v.x, v.y);
    *(__half2*)(d+2) = __floats2half2_rn(v.z, v.w);
}

// ---------------------------------------------------------------------------
// FP16 GEMM: C[M,N](fp32) = A[M,K](h) @ B[K,N](h). 128x128 tile, BK=32,
// warp tile 64x32 (4x2 m16n16k16 frags), cp.async double buffer.
// ---------------------------------------------------------------------------
#define AP_A 40            // halves
#define AP_B 136           // halves
#define A_STG (128*AP_A)   // halves per stage
#define B_STG (32*AP_B)
#define GEMM_SMEM ((2*A_STG + 2*B_STG) * 2)

__global__ void __launch_bounds__(256, 2) gemm_h(
    const __half* __restrict__ A, const __half* __restrict__ Bm,
    float* __restrict__ C, int M, int N, int K)
{
    extern __shared__ __half smh[];
    __half* As = smh;
    __half* Bs = smh + 2*A_STG;

    const int tid = threadIdx.x;
    const int bm = blockIdx.y * 128;
    const int bn = blockIdx.x * 128;
    const int w  = tid >> 5;
    const int wm = (w >> 2) * 64;
    const int wn = (w & 3) * 32;

    wmma::fragment<wmma::accumulator, 16, 16, 16, float> acc[4][2];
    #pragma unroll
    for (int i = 0; i < 4; i++)
        #pragma unroll
        for (int j = 0; j < 2; j++) wmma::fill_fragment(acc[i][j], 0.f);

    const int nk = K / 32;

    auto prefetch = [&](int kt, int stg) {
        const int k0 = kt * 32;
        __half* ad = As + stg * A_STG;
        __half* bd = Bs + stg * B_STG;
        #pragma unroll
        for (int i = 0; i < 2; i++) {              // A: 128x32 h = 512 chunks
            int id = tid + 256*i;
            int r = id >> 2, c = (id & 3) * 8;
            cp16(s2u(ad + r*AP_A + c), &A[(size_t)(bm + r) * K + k0 + c]);
        }
        #pragma unroll
        for (int i = 0; i < 2; i++) {              // B: 32x128 h = 512 chunks
            int id = tid + 256*i;
            int r = id >> 4, c = (id & 15) * 8;
            cp16(s2u(bd + r*AP_B + c), &Bm[(size_t)(k0 + r) * N + bn + c]);
        }
        cp_commit();
    };

    prefetch(0, 0);
    int stg = 0;

    for (int kt = 0; kt < nk; kt++) {
        cp_wait0();
        __syncthreads();
        if (kt + 1 < nk) prefetch(kt + 1, stg ^ 1);

        const __half* a0 = As + stg * A_STG;
        const __half* b0 = Bs + stg * B_STG;
        #pragma unroll
        for (int kk = 0; kk < 2; kk++) {
            wmma::fragment<wmma::matrix_a, 16, 16, 16, __half, wmma::row_major> af[4];
            wmma::fragment<wmma::matrix_b, 16, 16, 16, __half, wmma::row_major> bf[2];
            #pragma unroll
            for (int i = 0; i < 4; i++)
                wmma::load_matrix_sync(af[i], a0 + (wm + i*16)*AP_A + kk*16, AP_A);
            #pragma unroll
            for (int j = 0; j < 2; j++)
                wmma::load_matrix_sync(bf[j], b0 + (kk*16)*AP_B + wn + j*16, AP_B);
            #pragma unroll
            for (int i = 0; i < 4; i++)
                #pragma unroll
                for (int j = 0; j < 2; j++)
                    wmma::mma_sync(acc[i][j], af[i], bf[j], acc[i][j]);
        }
        stg ^= 1;
    }

    #pragma unroll
    for (int i = 0; i < 4; i++)
        #pragma unroll
        for (int j = 0; j < 2; j++)
            wmma::store_matrix_sync(&C[(size_t)(bm + wm + i*16) * N + bn + wn + j*16],
                                    acc[i][j], N, wmma::mem_row_major);
}

__global__ void __launch_bounds__(256) bias_add_kernel(
    float* __restrict__ out, const float* __restrict__ bias, int total4, int N)
{
    int idx = blockIdx.x * blockDim.x + threadIdx.x;
    if (idx >= total4) return;
    int col = (idx * 4) & (N - 1);
    float4 v = *(float4*)&out[idx * 4];
    v.x += bias[col+0]; v.y += bias[col+1];
    v.z += bias[col+2]; v.w += bias[col+3];
    *(float4*)&out[idx * 4] = v;
}

// ---------------------------------------------------------------------------
// RoPE + L2 norm: reads fp32 qkv, writes fp16 q (pre-scaled by 1/8) and k
// into g_qkvh. One warp per (b,t,h,q|k).
// ---------------------------------------------------------------------------
__global__ void __launch_bounds__(256) rope_norm_kernel(
    const float* __restrict__ qkv, __half* __restrict__ qkvh)
{
    const int gw = (blockIdx.x * blockDim.x + threadIdx.x) >> 5;
    const int lane = threadIdx.x & 31;
    const int which = gw & 1;
    const int h = (gw >> 1) & (Hn - 1);
    const int t = (gw >> 5) & (Tn - 1);
    const int b = gw >> 16;

    const size_t off = (size_t)(b*Tn + t) * QKVN + which*Dn + h*HDn;
    const float* p = qkv + off;
    __half* d = qkvh + off;

    const float inv_freq = exp2f(-(float)lane * (13.287712379549449f / 32.f));
    const float ang = (float)t * inv_freq;
    float s, c;
    sincosf(ang, &s, &c);

    const float x1 = p[lane];
    const float x2 = p[lane + 32];
    const float r1 = x1*c - x2*s;
    const float r2 = x1*s + x2*c;

    float ss = r1*r1 + r2*r2;
    #pragma unroll
    for (int off2 = 16; off2; off2 >>= 1)
        ss += __shfl_xor_sync(0xffffffffu, ss, off2);

    float inv = rsqrtf(ss + 1e-6f);
    if (which == 0) inv *= 0.125f;     // fold 1/sqrt(HD) into q (exact pow2)
    d[lane]      = __float2half(r1 * inv);
    d[lane + 32] = __float2half(r2 * inv);
}

// ---------------------------------------------------------------------------
// FP16 flash attention: 64 q-rows / 128 threads / 4 warps, cp.async double-
// buffered K/V (fp16). q,k unit vectors -> |S|<=0.125 -> exp without
// max/rescale. S staged fp32, P stored fp16, O accumulated fp32.
// smem ~73KB -> 3 blocks/SM.
// ---------------------------------------------------------------------------
#define APH 72                     // half pitch for Q/K/V/P tiles
#define SXP 68                     // float pitch for S/O staging
#define KV_STGH (64*APH)
#define SM_Q   0
#define SM_K   (SM_Q + 64*APH)                 // halves
#define SM_V   (SM_K + 2*KV_STGH)
#define SM_P   (SM_V + 2*KV_STGH)
#define SM_HALVES (SM_P + 64*APH)
#define SM_SX  0                               // floats, after halves region
#define ATT_SMEM (SM_HALVES*2 + 64*SXP*4 + 64*4)

__global__ void __launch_bounds__(128) attn_h_kernel(
    const __half* __restrict__ qkvh, __half* __restrict__ outp)
{
    extern __shared__ __half smh[];
    __half* Qs = smh + SM_Q;
    __half* Ks = smh + SM_K;
    __half* Vs = smh + SM_V;
    __half* Ph = smh + SM_P;
    float* Sx   = (float*)(smh + SM_HALVES);
    float* lrow = Sx + 64*SXP;

    const int tid  = threadIdx.x;
    const int w    = tid >> 5;
    const int lane = tid & 31;

    const int qt = blockIdx.x & 31;
    const int h  = (blockIdx.x >> 5) & (Hn-1);
    const int b  = blockIdx.x >> 9;
    const int q0 = qt * 64;

    const __half* qbase = qkvh + (size_t)(b*Tn) * QKVN + h*HDn;
    const __half* kbase = qbase + Dn;
    const __half* vbase = qbase + 2*Dn;

    auto prefetch_kv = [&](int kt, int stg) {
        __half* kd = Ks + stg*KV_STGH;
        __half* vd = Vs + stg*KV_STGH;
        #pragma unroll
        for (int i = 0; i < 4; i++) {          // 64x64 h = 512 chunks
            int id = tid + 128*i;
            int r = id >> 3, c = (id & 7) * 8;
            cp16(s2u(kd + r*APH + c), kbase + (size_t)(kt*64 + r) * QKVN + c);
        }
        #pragma unroll
        for (int i = 0; i < 4; i++) {
            int id = tid + 128*i;
            int r = id >> 3, c = (id & 7) * 8;
            cp16(s2u(vd + r*APH + c), vbase + (size_t)(kt*64 + r) * QKVN + c);
        }
        cp_commit();
    };

    // Q tile (already pre-scaled fp16) via cp.async
    #pragma unroll
    for (int i = 0; i < 4; i++) {
        int id = tid + 128*i;
        int r = id >> 3, c = (id & 7) * 8;
        cp16(s2u(Qs + r*APH + c), qbase + (size_t)(q0 + r) * QKVN + c);
    }
    cp_commit();
    prefetch_kv(0, 0);

    if (tid < 64) lrow[tid] = 0.f;

    wmma::fragment<wmma::accumulator, 16, 16, 16, float> oacc[4];
    #pragma unroll
    for (int j = 0; j < 4; j++) wmma::fill_fragment(oacc[j], 0.f);

    const int rowm = w * 16;
    int stg = 0;

    for (int kt = 0; kt < Tn/64; kt++) {
        cp_wait0();
        __syncthreads();
        if (kt + 1 < Tn/64) prefetch_kv(kt + 1, stg ^ 1);

        const __half* kc = Ks + stg*KV_STGH;
        const __half* vc = Vs + stg*KV_STGH;

        // S = Q @ K^T  (K [key][d] read col-major as [d][key])
        wmma::fragment<wmma::accumulator, 16, 16, 16, float> sacc[4];
        #pragma unroll
        for (int j = 0; j < 4; j++) wmma::fill_fragment(sacc[j], 0.f);
        #pragma unroll
        for (int ks = 0; ks < 4; ks++) {
            wmma::fragment<wmma::matrix_a, 16, 16, 16, __half, wmma::row_major> aq;
            wmma::load_matrix_sync(aq, Qs + rowm*APH + ks*16, APH);
            #pragma unroll
            for (int j = 0; j < 4; j++) {
                wmma::fragment<wmma::matrix_b, 16, 16, 16, __half, wmma::col_major> bk;
                wmma::load_matrix_sync(bk, kc + j*16*APH + ks*16, APH);
                wmma::mma_sync(sacc[j], aq, bk, sacc[j]);
            }
        }
        #pragma unroll
        for (int j = 0; j < 4; j++)
            wmma::store_matrix_sync(Sx + rowm*SXP + j*16, sacc[j], SXP, wmma::mem_row_major);
        __syncwarp();

        // P = half(exp(S)); row sums of the rounded values.
        {
            const int rr = rowm + (lane >> 1);
            const int cc = (lane & 1) * 32;
            const float* sr = Sx + rr*SXP + cc;
            __half* pr = Ph + rr*APH + cc;
            float sum = 0.f;
            #pragma unroll
            for (int j = 0; j < 32; j += 2) {
                float e0 = __expf(sr[j]);
                float e1 = __expf(sr[j+1]);
                __half2 hp = __floats2half2_rn(e0, e1);
                *(__half2*)(pr + j) = hp;
                sum += __half2float(__low2half(hp)) + __half2float(__high2half(hp));
            }
            sum += __shfl_xor_sync(0xffffffffu, sum, 1);
            if (!(lane & 1)) lrow[rr] += sum;
        }
        __syncwarp();

        // O += P @ V
        #pragma unroll
        for (int ks = 0; ks < 4; ks++) {
            wmma::fragment<wmma::matrix_a, 16, 16, 16, __half, wmma::row_major> ap;
            wmma::load_matrix_sync(ap, Ph + rowm*APH + ks*16, APH);
            #pragma unroll
            for (int j = 0; j < 4; j++) {
                wmma::fragment<wmma::matrix_b, 16, 16, 16, __half, wmma::row_major> bv;
                wmma::load_matrix_sync(bv, vc + ks*16*APH + j*16, APH);
                wmma::mma_sync(oacc[j], ap, bv, oacc[j]);
            }
        }
        stg ^= 1;
    }

    __syncthreads();
    #pragma unroll
    for (int j = 0; j < 4; j++)
        wmma::store_matrix_sync(Sx + rowm*SXP + j*16, oacc[j], SXP, wmma::mem_row_major);
    __syncthreads();

    {
        const int r  = tid >> 1;
        const int c0 = (tid & 1) * 32;
        const float inv = 1.f / lrow[r];
        const float* srcr = Sx + r*SXP + c0;
        __half* dst = outp + (size_t)(b*Tn + q0 + r) * Dn + h*HDn + c0;
        #pragma unroll
        for (int j = 0; j < 32; j += 2)
            *(__half2*)(dst + j) = __floats2half2_rn(srcr[j] * inv, srcr[j+1] * inv);
    }
}

// ---------------------------------------------------------------------------
extern "C" void kernel_launch(void* const* d_in, const int* in_sizes, int n_in,
                              void* d_out, int out_size)
{
    const float* x    = (const float*)d_in[0];
    const float* Wqkv = (const float*)d_in[1];
    const float* Wo   = (const float*)d_in[2];
    const float* bo   = (const float*)d_in[3];
    float* out = (float*)d_out;

    float *qkv;
    __half *qkvh, *atth, *xh, *wqh, *woh;
    cudaGetSymbolAddress((void**)&qkv,  g_qkv);
    cudaGetSymbolAddress((void**)&qkvh, g_qkvh);
    cudaGetSymbolAddress((void**)&atth, g_atth);
    cudaGetSymbolAddress((void**)&xh,   g_xh);
    cudaGetSymbolAddress((void**)&wqh,  g_wqh);
    cudaGetSymbolAddress((void**)&woh,  g_woh);

    cudaFuncSetAttribute(gemm_h,
                         cudaFuncAttributeMaxDynamicSharedMemorySize, GEMM_SMEM);
    cudaFuncSetAttribute(attn_h_kernel,
                         cudaFuncAttributeMaxDynamicSharedMemorySize, ATT_SMEM);

    // 0) fp16 conversions of inputs
    {
        int n4;
        n4 = MROWS*Dn/4;  f2h_kernel<<<(n4+255)/256, 256>>>(x,    xh,  n4);
        n4 = Dn*QKVN/4;   f2h_kernel<<<(n4+255)/256, 256>>>(Wqkv, wqh, n4);
        n4 = Dn*Dn/4;     f2h_kernel<<<(n4+255)/256, 256>>>(Wo,   woh, n4);
    }
    // 1) qkv(fp32) = xh @ wqh
    {
        dim3 grid(QKVN/128, MROWS/128);
        gemm_h<<<grid, 256, GEMM_SMEM>>>(xh, wqh, qkv, MROWS, QKVN, Dn);
    }
    // 2) RoPE + L2 norm -> fp16 q (prescaled), k ; v converted separately
    {
        int warps = Bn*Tn*Hn*2;
        rope_norm_kernel<<<warps/8, 256>>>(qkv, qkvh);
        int n4 = MROWS*Dn/4;
        vconv_kernel<<<(n4+255)/256, 256>>>(qkv, qkvh);
    }
    // 3) attention (fp16 in/out)
    {
        dim3 grid(Bn * Hn * (Tn/64));   // 2048
        attn_h_kernel<<<grid, 128, ATT_SMEM>>>(qkvh, atth);
    }
    // 4) out = atth @ woh + bo
    {
        dim3 grid(Dn/128, MROWS/128);
        gemm_h<<<grid, 256, GEMM_SMEM>>>(atth, woh, out, MROWS, Dn, Dn);
        int total4 = MROWS * Dn / 4;
        bias_add_kernel<<<(total4 + 255)/256, 256>>>(out, bo, total4, Dn);
    }
}

// round 12
// speedup vs baseline: 3.4669x; 1.0801x over previous
#include <cuda_runtime.h>
#include <cuda_fp16.h>
#include <mma.h>
#include <math.h>
#include <stdint.h>

using namespace nvcuda;

#define Bn 4
#define Tn 2048
#define Dn 1024
#define Hn 16
#define HDn 64
#define MROWS (Bn*Tn)      // 8192
#define QKVN (3*Dn)        // 3072

__device__ float  g_qkv[(size_t)MROWS * QKVN];    // GEMM1 output (fp32)
__device__ __half g_qkvh[(size_t)MROWS * QKVN];   // fp16 q(prescaled),k,v
__device__ __half g_atth[(size_t)MROWS * Dn];     // attention output (fp16)
__device__ __half g_xh[(size_t)MROWS * Dn];
__device__ __half g_wqh[(size_t)Dn * QKVN];
__device__ __half g_woh[(size_t)Dn * Dn];

__device__ __forceinline__ uint32_t s2u(const void* p) {
    return (uint32_t)__cvta_generic_to_shared(p);
}
__device__ __forceinline__ void cp16(uint32_t dst, const void* src) {
    asm volatile("cp.async.cg.shared.global [%0], [%1], 16;" :: "r"(dst), "l"(src));
}
__device__ __forceinline__ void cp_commit() { asm volatile("cp.async.commit_group;"); }
__device__ __forceinline__ void cp_wait0()  { asm volatile("cp.async.wait_group 0;"); }

__global__ void __launch_bounds__(256) f2h_kernel(
    const float* __restrict__ src, __half* __restrict__ dst, int total4)
{
    int idx = blockIdx.x * blockDim.x + threadIdx.x;
    if (idx >= total4) return;
    float4 v = *(const float4*)&src[idx * 4];
    *(__half2*)&dst[idx*4]   = __floats2half2_rn(v.x, v.y);
    *(__half2*)&dst[idx*4+2] = __floats2half2_rn(v.z, v.w);
}

__global__ void __launch_bounds__(256) vconv_kernel(
    const float* __restrict__ qkv, __half* __restrict__ qkvh)
{
    int idx = blockIdx.x * blockDim.x + threadIdx.x;
    if (idx >= MROWS*Dn/4) return;
    int row = idx >> 8;
    int col = (idx & 255) * 4;
    const float* s = qkv + (size_t)row * QKVN + 2*Dn + col;
    __half* d = qkvh + (size_t)row * QKVN + 2*Dn + col;
    float4 v = *(const float4*)s;
    *(__half2*)d     = __floats2half2_rn(v.x, v.y);
    *(__half2*)(d+2) = __floats2half2_rn(v.z, v.w);
}

// ---------------------------------------------------------------------------
// FP16 GEMM: 128x128 tile, BK=64, warp tile 64x32, cp.async double buffer.
// ---------------------------------------------------------------------------
#define AP_A 72            // halves (64+8)
#define AP_B 136           // halves (128+8)
#define A_STG (128*AP_A)
#define B_STG (64*AP_B)
#define GEMM_SMEM ((2*A_STG + 2*B_STG) * 2)

__global__ void __launch_bounds__(256, 2) gemm_h(
    const __half* __restrict__ A, const __half* __restrict__ Bm,
    float* __restrict__ C, int M, int N, int K)
{
    extern __shared__ __half smh[];
    __half* As = smh;
    __half* Bs = smh + 2*A_STG;

    const int tid = threadIdx.x;
    const int bm = blockIdx.y * 128;
    const int bn = blockIdx.x * 128;
    const int w  = tid >> 5;
    const int wm = (w >> 2) * 64;
    const int wn = (w & 3) * 32;

    wmma::fragment<wmma::accumulator, 16, 16, 16, float> acc[4][2];
    #pragma unroll
    for (int i = 0; i < 4; i++)
        #pragma unroll
        for (int j = 0; j < 2; j++) wmma::fill_fragment(acc[i][j], 0.f);

    const int nk = K / 64;

    auto prefetch = [&](int kt, int stg) {
        const int k0 = kt * 64;
        __half* ad = As + stg * A_STG;
        __half* bd = Bs + stg * B_STG;
        #pragma unroll
        for (int i = 0; i < 4; i++) {          // A: 128x64 h = 1024 chunks
            int id = tid + 256*i;
            int r = id >> 3, c = (id & 7) * 8;
            cp16(s2u(ad + r*AP_A + c), &A[(size_t)(bm + r) * K + k0 + c]);
        }
        #pragma unroll
        for (int i = 0; i < 4; i++) {          // B: 64x128 h = 1024 chunks
            int id = tid + 256*i;
            int r = id >> 4, c = (id & 15) * 8;
            cp16(s2u(bd + r*AP_B + c), &Bm[(size_t)(k0 + r) * N + bn + c]);
        }
        cp_commit();
    };

    prefetch(0, 0);
    int stg = 0;

    for (int kt = 0; kt < nk; kt++) {
        cp_wait0();
        __syncthreads();
        if (kt + 1 < nk) prefetch(kt + 1, stg ^ 1);

        const __half* a0 = As + stg * A_STG;
        const __half* b0 = Bs + stg * B_STG;
        #pragma unroll
        for (int kk = 0; kk < 4; kk++) {
            wmma::fragment<wmma::matrix_a, 16, 16, 16, __half, wmma::row_major> af[4];
            wmma::fragment<wmma::matrix_b, 16, 16, 16, __half, wmma::row_major> bf[2];
            #pragma unroll
            for (int i = 0; i < 4; i++)
                wmma::load_matrix_sync(af[i], a0 + (wm + i*16)*AP_A + kk*16, AP_A);
            #pragma unroll
            for (int j = 0; j < 2; j++)
                wmma::load_matrix_sync(bf[j], b0 + (kk*16)*AP_B + wn + j*16, AP_B);
            #pragma unroll
            for (int i = 0; i < 4; i++)
                #pragma unroll
                for (int j = 0; j < 2; j++)
                    wmma::mma_sync(acc[i][j], af[i], bf[j], acc[i][j]);
        }
        stg ^= 1;
    }

    #pragma unroll
    for (int i = 0; i < 4; i++)
        #pragma unroll
        for (int j = 0; j < 2; j++)
            wmma::store_matrix_sync(&C[(size_t)(bm + wm + i*16) * N + bn + wn + j*16],
                                    acc[i][j], N, wmma::mem_row_major);
}

__global__ void __launch_bounds__(256) bias_add_kernel(
    float* __restrict__ out, const float* __restrict__ bias, int total4, int N)
{
    int idx = blockIdx.x * blockDim.x + threadIdx.x;
    if (idx >= total4) return;
    int col = (idx * 4) & (N - 1);
    float4 v = *(float4*)&out[idx * 4];
    v.x += bias[col+0]; v.y += bias[col+1];
    v.z += bias[col+2]; v.w += bias[col+3];
    *(float4*)&out[idx * 4] = v;
}

// ---------------------------------------------------------------------------
// RoPE + L2 norm: fp32 in, fp16 out (q pre-scaled by 1/8).
// ---------------------------------------------------------------------------
__global__ void __launch_bounds__(256) rope_norm_kernel(
    const float* __restrict__ qkv, __half* __restrict__ qkvh)
{
    const int gw = (blockIdx.x * blockDim.x + threadIdx.x) >> 5;
    const int lane = threadIdx.x & 31;
    const int which = gw & 1;
    const int h = (gw >> 1) & (Hn - 1);
    const int t = (gw >> 5) & (Tn - 1);
    const int b = gw >> 16;

    const size_t off = (size_t)(b*Tn + t) * QKVN + which*Dn + h*HDn;
    const float* p = qkv + off;
    __half* d = qkvh + off;

    const float inv_freq = exp2f(-(float)lane * (13.287712379549449f / 32.f));
    const float ang = (float)t * inv_freq;
    float s, c;
    sincosf(ang, &s, &c);

    const float x1 = p[lane];
    const float x2 = p[lane + 32];
    const float r1 = x1*c - x2*s;
    const float r2 = x1*s + x2*c;

    float ss = r1*r1 + r2*r2;
    #pragma unroll
    for (int off2 = 16; off2; off2 >>= 1)
        ss += __shfl_xor_sync(0xffffffffu, ss, off2);

    float inv = rsqrtf(ss + 1e-6f);
    if (which == 0) inv *= 0.125f;
    d[lane]      = __float2half(r1 * inv);
    d[lane + 32] = __float2half(r2 * inv);
}

// ---------------------------------------------------------------------------
// FP16 flash attention: 128 q-rows / 256 threads / 8 warps per block.
// Warp w owns rows 16w..16w+15, all 64 keys. K/V fill traffic amortized
// over 2x rows vs 64-row blocks. smem ~109KB -> 2 blocks/SM.
// ---------------------------------------------------------------------------
#define APH 72                     // half pitch
#define SXP 68                     // float pitch
#define KV_STGH (64*APH)
#define SM_Q   0
#define SM_K   (SM_Q + 128*APH)
#define SM_V   (SM_K + 2*KV_STGH)
#define SM_P   (SM_V + 2*KV_STGH)
#define SM_HALVES (SM_P + 128*APH)
#define ATT_SMEM (SM_HALVES*2 + 128*SXP*4 + 128*4)

__global__ void __launch_bounds__(256) attn_h_kernel(
    const __half* __restrict__ qkvh, __half* __restrict__ outp)
{
    extern __shared__ __half smh[];
    __half* Qs = smh + SM_Q;
    __half* Ks = smh + SM_K;
    __half* Vs = smh + SM_V;
    __half* Ph = smh + SM_P;
    float* Sx   = (float*)(smh + SM_HALVES);
    float* lrow = Sx + 128*SXP;

    const int tid  = threadIdx.x;
    const int w    = tid >> 5;
    const int lane = tid & 31;

    const int qt = blockIdx.x & 15;            // 16 q tiles of 128
    const int h  = (blockIdx.x >> 4) & (Hn-1);
    const int b  = blockIdx.x >> 8;
    const int q0 = qt * 128;

    const __half* qbase = qkvh + (size_t)(b*Tn) * QKVN + h*HDn;
    const __half* kbase = qbase + Dn;
    const __half* vbase = qbase + 2*Dn;

    auto prefetch_kv = [&](int kt, int stg) {
        __half* kd = Ks + stg*KV_STGH;
        __half* vd = Vs + stg*KV_STGH;
        #pragma unroll
        for (int i = 0; i < 2; i++) {          // K: 64x64 h = 512 chunks
            int id = tid + 256*i;
            int r = id >> 3, c = (id & 7) * 8;
            cp16(s2u(kd + r*APH + c), kbase + (size_t)(kt*64 + r) * QKVN + c);
        }
        #pragma unroll
        for (int i = 0; i < 2; i++) {
            int id = tid + 256*i;
            int r = id >> 3, c = (id & 7) * 8;
            cp16(s2u(vd + r*APH + c), vbase + (size_t)(kt*64 + r) * QKVN + c);
        }
        cp_commit();
    };

    // Q tile: 128x64 h = 1024 chunks
    #pragma unroll
    for (int i = 0; i < 4; i++) {
        int id = tid + 256*i;
        int r = id >> 3, c = (id & 7) * 8;
        cp16(s2u(Qs + r*APH + c), qbase + (size_t)(q0 + r) * QKVN + c);
    }
    cp_commit();
    prefetch_kv(0, 0);

    if (tid < 128) lrow[tid] = 0.f;

    wmma::fragment<wmma::accumulator, 16, 16, 16, float> oacc[4];
    #pragma unroll
    for (int j = 0; j < 4; j++) wmma::fill_fragment(oacc[j], 0.f);

    const int rowm = w * 16;
    int stg = 0;

    for (int kt = 0; kt < Tn/64; kt++) {
        cp_wait0();
        __syncthreads();
        if (kt + 1 < Tn/64) prefetch_kv(kt + 1, stg ^ 1);

        const __half* kc = Ks + stg*KV_STGH;
        const __half* vc = Vs + stg*KV_STGH;

        // S = Q @ K^T
        wmma::fragment<wmma::accumulator, 16, 16, 16, float> sacc[4];
        #pragma unroll
        for (int j = 0; j < 4; j++) wmma::fill_fragment(sacc[j], 0.f);
        #pragma unroll
        for (int ks = 0; ks < 4; ks++) {
            wmma::fragment<wmma::matrix_a, 16, 16, 16, __half, wmma::row_major> aq;
            wmma::load_matrix_sync(aq, Qs + rowm*APH + ks*16, APH);
            #pragma unroll
            for (int j = 0; j < 4; j++) {
                wmma::fragment<wmma::matrix_b, 16, 16, 16, __half, wmma::col_major> bk;
                wmma::load_matrix_sync(bk, kc + j*16*APH + ks*16, APH);
                wmma::mma_sync(sacc[j], aq, bk, sacc[j]);
            }
        }
        #pragma unroll
        for (int j = 0; j < 4; j++)
            wmma::store_matrix_sync(Sx + rowm*SXP + j*16, sacc[j], SXP, wmma::mem_row_major);
        __syncwarp();

        // P = half(exp(S)); row sums. (rows tid>>1 are within this warp's 16)
        {
            const int rr = rowm + (lane >> 1);
            const int cc = (lane & 1) * 32;
            const float* sr = Sx + rr*SXP + cc;
            __half* pr = Ph + rr*APH + cc;
            float sum = 0.f;
            #pragma unroll
            for (int j = 0; j < 32; j += 2) {
                float e0 = __expf(sr[j]);
                float e1 = __expf(sr[j+1]);
                __half2 hp = __floats2half2_rn(e0, e1);
                *(__half2*)(pr + j) = hp;
                sum += __half2float(__low2half(hp)) + __half2float(__high2half(hp));
            }
            sum += __shfl_xor_sync(0xffffffffu, sum, 1);
            if (!(lane & 1)) lrow[rr] += sum;
        }
        __syncwarp();

        // O += P @ V
        #pragma unroll
        for (int ks = 0; ks < 4; ks++) {
            wmma::fragment<wmma::matrix_a, 16, 16, 16, __half, wmma::row_major> ap;
            wmma::load_matrix_sync(ap, Ph + rowm*APH + ks*16, APH);
            #pragma unroll
            for (int j = 0; j < 4; j++) {
                wmma::fragment<wmma::matrix_b, 16, 16, 16, __half, wmma::row_major> bv;
                wmma::load_matrix_sync(bv, vc + ks*16*APH + j*16, APH);
                wmma::mma_sync(oacc[j], ap, bv, oacc[j]);
            }
        }
        stg ^= 1;
    }

    __syncthreads();
    #pragma unroll
    for (int j = 0; j < 4; j++)
        wmma::store_matrix_sync(Sx + rowm*SXP + j*16, oacc[j], SXP, wmma::mem_row_major);
    __syncthreads();

    {
        const int r  = tid >> 1;
        const int c0 = (tid & 1) * 32;
        const float inv = 1.f / lrow[r];
        const float* srcr = Sx + r*SXP + c0;
        __half* dst = outp + (size_t)(b*Tn + q0 + r) * Dn + h*HDn + c0;
        #pragma unroll
        for (int j = 0; j < 32; j += 2)
            *(__half2*)(dst + j) = __floats2half2_rn(srcr[j] * inv, srcr[j+1] * inv);
    }
}

// ---------------------------------------------------------------------------
extern "C" void kernel_launch(void* const* d_in, const int* in_sizes, int n_in,
                              void* d_out, int out_size)
{
    const float* x    = (const float*)d_in[0];
    const float* Wqkv = (const float*)d_in[1];
    const float* Wo   = (const float*)d_in[2];
    const float* bo   = (const float*)d_in[3];
    float* out = (float*)d_out;

    float *qkv;
    __half *qkvh, *atth, *xh, *wqh, *woh;
    cudaGetSymbolAddress((void**)&qkv,  g_qkv);
    cudaGetSymbolAddress((void**)&qkvh, g_qkvh);
    cudaGetSymbolAddress((void**)&atth, g_atth);
    cudaGetSymbolAddress((void**)&xh,   g_xh);
    cudaGetSymbolAddress((void**)&wqh,  g_wqh);
    cudaGetSymbolAddress((void**)&woh,  g_woh);

    cudaFuncSetAttribute(gemm_h,
                         cudaFuncAttributeMaxDynamicSharedMemorySize, GEMM_SMEM);
    cudaFuncSetAttribute(attn_h_kernel,
                         cudaFuncAttributeMaxDynamicSharedMemorySize, ATT_SMEM);

    // 0) fp16 conversions of inputs
    {
        int n4;
        n4 = MROWS*Dn/4;  f2h_kernel<<<(n4+255)/256, 256>>>(x,    xh,  n4);
        n4 = Dn*QKVN/4;   f2h_kernel<<<(n4+255)/256, 256>>>(Wqkv, wqh, n4);
        n4 = Dn*Dn/4;     f2h_kernel<<<(n4+255)/256, 256>>>(Wo,   woh, n4);
    }
    // 1) qkv(fp32) = xh @ wqh
    {
        dim3 grid(QKVN/128, MROWS/128);
        gemm_h<<<grid, 256, GEMM_SMEM>>>(xh, wqh, qkv, MROWS, QKVN, Dn);
    }
    // 2) RoPE + L2 norm -> fp16 q(prescaled), k; v converted separately
    {
        int warps = Bn*Tn*Hn*2;
        rope_norm_kernel<<<warps/8, 256>>>(qkv, qkvh);
        int n4 = MROWS*Dn/4;
        vconv_kernel<<<(n4+255)/256, 256>>>(qkv, qkvh);
    }
    // 3) attention
    {
        dim3 grid(Bn * Hn * (Tn/128));   // 1024
        attn_h_kernel<<<grid, 256, ATT_SMEM>>>(qkvh, atth);
    }
    // 4) out = atth @ woh + bo
    {
        dim3 grid(Dn/128, MROWS/128);
        gemm_h<<<grid, 256, GEMM_SMEM>>>(atth, woh, out, MROWS, Dn, Dn);
        int total4 = MROWS * Dn / 4;
        bias_add_kernel<<<(total4 + 255)/256, 256>>>(out, bo, total4, Dn);
    }
}

// round 13
// speedup vs baseline: 3.4863x; 1.0056x over previous
#include <cuda_runtime.h>
#include <cuda_fp16.h>
#include <mma.h>
#include <math.h>
#include <stdint.h>

using namespace nvcuda;

#define Bn 4
#define Tn 2048
#define Dn 1024
#define Hn 16
#define HDn 64
#define MROWS (Bn*Tn)      // 8192
#define QKVN (3*Dn)        // 3072

__device__ __half g_qkvh[(size_t)MROWS * QKVN];   // fp16 qkv (q prescaled post-rope)
__device__ __half g_atth[(size_t)MROWS * Dn];     // attention output (fp16)
__device__ __half g_xh[(size_t)MROWS * Dn];
__device__ __half g_wqh[(size_t)Dn * QKVN];
__device__ __half g_woh[(size_t)Dn * Dn];

__device__ __forceinline__ uint32_t s2u(const void* p) {
    return (uint32_t)__cvta_generic_to_shared(p);
}
__device__ __forceinline__ void cp16(uint32_t dst, const void* src) {
    asm volatile("cp.async.cg.shared.global [%0], [%1], 16;" :: "r"(dst), "l"(src));
}
__device__ __forceinline__ void cp_commit() { asm volatile("cp.async.commit_group;"); }
__device__ __forceinline__ void cp_wait0()  { asm volatile("cp.async.wait_group 0;"); }

__global__ void __launch_bounds__(256) f2h_kernel(
    const float* __restrict__ src, __half* __restrict__ dst, int total4)
{
    int idx = blockIdx.x * blockDim.x + threadIdx.x;
    if (idx >= total4) return;
    float4 v = *(const float4*)&src[idx * 4];
    *(__half2*)&dst[idx*4]   = __floats2half2_rn(v.x, v.y);
    *(__half2*)&dst[idx*4+2] = __floats2half2_rn(v.z, v.w);
}

// ---------------------------------------------------------------------------
// FP16 GEMM: 128x128 tile, BK=64, warp tile 64x32, cp.async double buffer.
// Epilogue stages fp32 acc through (now free) pipeline smem:
//   OUT_HALF=1 -> half2 stores to __half C;  OUT_HALF=0 -> float4 + bias.
// ---------------------------------------------------------------------------
#define AP_A 72            // halves (64+8)
#define AP_B 136           // halves (128+8)
#define A_STG (128*AP_A)
#define B_STG (64*AP_B)
#define GEMM_SMEM ((2*A_STG + 2*B_STG) * 2)   // 71680 B; staging 128*132*4=67584 fits
#define SP 132

template <int OUT_HALF, int WITH_BIAS>
__global__ void __launch_bounds__(256, 2) gemm_h(
    const __half* __restrict__ A, const __half* __restrict__ Bm,
    const float* __restrict__ bias,
    __half* __restrict__ Ch, float* __restrict__ Cf,
    int M, int N, int K)
{
    extern __shared__ __half smh[];
    __half* As = smh;
    __half* Bs = smh + 2*A_STG;

    const int tid = threadIdx.x;
    const int bm = blockIdx.y * 128;
    const int bn = blockIdx.x * 128;
    const int w  = tid >> 5;
    const int wm = (w >> 2) * 64;
    const int wn = (w & 3) * 32;

    wmma::fragment<wmma::accumulator, 16, 16, 16, float> acc[4][2];
    #pragma unroll
    for (int i = 0; i < 4; i++)
        #pragma unroll
        for (int j = 0; j < 2; j++) wmma::fill_fragment(acc[i][j], 0.f);

    const int nk = K / 64;

    auto prefetch = [&](int kt, int stg) {
        const int k0 = kt * 64;
        __half* ad = As + stg * A_STG;
        __half* bd = Bs + stg * B_STG;
        #pragma unroll
        for (int i = 0; i < 4; i++) {
            int id = tid + 256*i;
            int r = id >> 3, c = (id & 7) * 8;
            cp16(s2u(ad + r*AP_A + c), &A[(size_t)(bm + r) * K + k0 + c]);
        }
        #pragma unroll
        for (int i = 0; i < 4; i++) {
            int id = tid + 256*i;
            int r = id >> 4, c = (id & 15) * 8;
            cp16(s2u(bd + r*AP_B + c), &Bm[(size_t)(k0 + r) * N + bn + c]);
        }
        cp_commit();
    };

    prefetch(0, 0);
    int stg = 0;

    for (int kt = 0; kt < nk; kt++) {
        cp_wait0();
        __syncthreads();
        if (kt + 1 < nk) prefetch(kt + 1, stg ^ 1);

        const __half* a0 = As + stg * A_STG;
        const __half* b0 = Bs + stg * B_STG;
        #pragma unroll
        for (int kk = 0; kk < 4; kk++) {
            wmma::fragment<wmma::matrix_a, 16, 16, 16, __half, wmma::row_major> af[4];
            wmma::fragment<wmma::matrix_b, 16, 16, 16, __half, wmma::row_major> bf[2];
            #pragma unroll
            for (int i = 0; i < 4; i++)
                wmma::load_matrix_sync(af[i], a0 + (wm + i*16)*AP_A + kk*16, AP_A);
            #pragma unroll
            for (int j = 0; j < 2; j++)
                wmma::load_matrix_sync(bf[j], b0 + (kk*16)*AP_B + wn + j*16, AP_B);
            #pragma unroll
            for (int i = 0; i < 4; i++)
                #pragma unroll
                for (int j = 0; j < 2; j++)
                    wmma::mma_sync(acc[i][j], af[i], bf[j], acc[i][j]);
        }
        stg ^= 1;
    }

    // Staged epilogue through smem (pipeline buffers are dead now)
    __syncthreads();
    float* stage = reinterpret_cast<float*>(smh);     // 128 x SP
    #pragma unroll
    for (int i = 0; i < 4; i++)
        #pragma unroll
        for (int j = 0; j < 2; j++)
            wmma::store_matrix_sync(stage + (wm + i*16)*SP + wn + j*16,
                                    acc[i][j], SP, wmma::mem_row_major);
    __syncthreads();

    #pragma unroll
    for (int it = 0; it < 8; it++) {
        int idx = tid + 256*it;          // 0..2047, 8 elems each
        int r = idx >> 4;                // 0..127
        int c = (idx & 15) * 8;          // 0..120
        const float* srow = stage + r*SP + c;
        if (OUT_HALF) {
            __half* dst = Ch + (size_t)(bm + r) * N + bn + c;
            #pragma unroll
            for (int k = 0; k < 4; k++)
                *(__half2*)(dst + 2*k) = __floats2half2_rn(srow[2*k], srow[2*k+1]);
        } else {
            float* dst = Cf + (size_t)(bm + r) * N + bn + c;
            float4 v0 = *(const float4*)(srow);
            float4 v1 = *(const float4*)(srow + 4);
            if (WITH_BIAS) {
                const float* bp = bias + bn + c;
                v0.x += bp[0]; v0.y += bp[1]; v0.z += bp[2]; v0.w += bp[3];
                v1.x += bp[4]; v1.y += bp[5]; v1.z += bp[6]; v1.w += bp[7];
            }
            *(float4*)(dst)     = v0;
            *(float4*)(dst + 4) = v1;
        }
    }
}

// ---------------------------------------------------------------------------
// RoPE + L2 norm: fp16 in/out, in place (q pre-scaled by 1/8).
// ---------------------------------------------------------------------------
__global__ void __launch_bounds__(256) rope_norm_kernel(__half* __restrict__ qkvh)
{
    const int gw = (blockIdx.x * blockDim.x + threadIdx.x) >> 5;
    const int lane = threadIdx.x & 31;
    const int which = gw & 1;
    const int h = (gw >> 1) & (Hn - 1);
    const int t = (gw >> 5) & (Tn - 1);
    const int b = gw >> 16;

    __half* d = qkvh + (size_t)(b*Tn + t) * QKVN + which*Dn + h*HDn;

    const float inv_freq = exp2f(-(float)lane * (13.287712379549449f / 32.f));
    const float ang = (float)t * inv_freq;
    float s, c;
    sincosf(ang, &s, &c);

    const float x1 = __half2float(d[lane]);
    const float x2 = __half2float(d[lane + 32]);
    const float r1 = x1*c - x2*s;
    const float r2 = x1*s + x2*c;

    float ss = r1*r1 + r2*r2;
    #pragma unroll
    for (int off2 = 16; off2; off2 >>= 1)
        ss += __shfl_xor_sync(0xffffffffu, ss, off2);

    float inv = rsqrtf(ss + 1e-6f);
    if (which == 0) inv *= 0.125f;     // fold 1/sqrt(HD) into q (exact pow2)
    d[lane]      = __float2half(r1 * inv);
    d[lane + 32] = __float2half(r2 * inv);
}

// ---------------------------------------------------------------------------
// FP16 flash attention: 128 q-rows / 256 threads / 8 warps (R12 config).
// q,k unit vectors -> |S|<=0.125 -> exp without max/rescale.
// ---------------------------------------------------------------------------
#define APH 72
#define SXP 68
#define KV_STGH (64*APH)
#define SM_Q   0
#define SM_K   (SM_Q + 128*APH)
#define SM_V   (SM_K + 2*KV_STGH)
#define SM_P   (SM_V + 2*KV_STGH)
#define SM_HALVES (SM_P + 128*APH)
#define ATT_SMEM (SM_HALVES*2 + 128*SXP*4 + 128*4)

__global__ void __launch_bounds__(256) attn_h_kernel(
    const __half* __restrict__ qkvh, __half* __restrict__ outp)
{
    extern __shared__ __half smh[];
    __half* Qs = smh + SM_Q;
    __half* Ks = smh + SM_K;
    __half* Vs = smh + SM_V;
    __half* Ph = smh + SM_P;
    float* Sx   = (float*)(smh + SM_HALVES);
    float* lrow = Sx + 128*SXP;

    const int tid  = threadIdx.x;
    const int w    = tid >> 5;
    const int lane = tid & 31;

    const int qt = blockIdx.x & 15;
    const int h  = (blockIdx.x >> 4) & (Hn-1);
    const int b  = blockIdx.x >> 8;
    const int q0 = qt * 128;

    const __half* qbase = qkvh + (size_t)(b*Tn) * QKVN + h*HDn;
    const __half* kbase = qbase + Dn;
    const __half* vbase = qbase + 2*Dn;

    auto prefetch_kv = [&](int kt, int stg) {
        __half* kd = Ks + stg*KV_STGH;
        __half* vd = Vs + stg*KV_STGH;
        #pragma unroll
        for (int i = 0; i < 2; i++) {
            int id = tid + 256*i;
            int r = id >> 3, c = (id & 7) * 8;
            cp16(s2u(kd + r*APH + c), kbase + (size_t)(kt*64 + r) * QKVN + c);
        }
        #pragma unroll
        for (int i = 0; i < 2; i++) {
            int id = tid + 256*i;
            int r = id >> 3, c = (id & 7) * 8;
            cp16(s2u(vd + r*APH + c), vbase + (size_t)(kt*64 + r) * QKVN + c);
        }
        cp_commit();
    };

    #pragma unroll
    for (int i = 0; i < 4; i++) {
        int id = tid + 256*i;
        int r = id >> 3, c = (id & 7) * 8;
        cp16(s2u(Qs + r*APH + c), qbase + (size_t)(q0 + r) * QKVN + c);
    }
    cp_commit();
    prefetch_kv(0, 0);

    if (tid < 128) lrow[tid] = 0.f;

    wmma::fragment<wmma::accumulator, 16, 16, 16, float> oacc[4];
    #pragma unroll
    for (int j = 0; j < 4; j++) wmma::fill_fragment(oacc[j], 0.f);

    const int rowm = w * 16;
    int stg = 0;

    for (int kt = 0; kt < Tn/64; kt++) {
        cp_wait0();
        __syncthreads();
        if (kt + 1 < Tn/64) prefetch_kv(kt + 1, stg ^ 1);

        const __half* kc = Ks + stg*KV_STGH;
        const __half* vc = Vs + stg*KV_STGH;

        wmma::fragment<wmma::accumulator, 16, 16, 16, float> sacc[4];
        #pragma unroll
        for (int j = 0; j < 4; j++) wmma::fill_fragment(sacc[j], 0.f);
        #pragma unroll
        for (int ks = 0; ks < 4; ks++) {
            wmma::fragment<wmma::matrix_a, 16, 16, 16, __half, wmma::row_major> aq;
            wmma::load_matrix_sync(aq, Qs + rowm*APH + ks*16, APH);
            #pragma unroll
            for (int j = 0; j < 4; j++) {
                wmma::fragment<wmma::matrix_b, 16, 16, 16, __half, wmma::col_major> bk;
                wmma::load_matrix_sync(bk, kc + j*16*APH + ks*16, APH);
                wmma::mma_sync(sacc[j], aq, bk, sacc[j]);
            }
        }
        #pragma unroll
        for (int j = 0; j < 4; j++)
            wmma::store_matrix_sync(Sx + rowm*SXP + j*16, sacc[j], SXP, wmma::mem_row_major);
        __syncwarp();

        {
            const int rr = rowm + (lane >> 1);
            const int cc = (lane & 1) * 32;
            const float* sr = Sx + rr*SXP + cc;
            __half* pr = Ph + rr*APH + cc;
            float sum = 0.f;
            #pragma unroll
            for (int j = 0; j < 32; j += 2) {
                float e0 = __expf(sr[j]);
                float e1 = __expf(sr[j+1]);
                __half2 hp = __floats2half2_rn(e0, e1);
                *(__half2*)(pr + j) = hp;
                sum += __half2float(__low2half(hp)) + __half2float(__high2half(hp));
            }
            sum += __shfl_xor_sync(0xffffffffu, sum, 1);
            if (!(lane & 1)) lrow[rr] += sum;
        }
        __syncwarp();

        #pragma unroll
        for (int ks = 0; ks < 4; ks++) {
            wmma::fragment<wmma::matrix_a, 16, 16, 16, __half, wmma::row_major> ap;
            wmma::load_matrix_sync(ap, Ph + rowm*APH + ks*16, APH);
            #pragma unroll
            for (int j = 0; j < 4; j++) {
                wmma::fragment<wmma::matrix_b, 16, 16, 16, __half, wmma::row_major> bv;
                wmma::load_matrix_sync(bv, vc + ks*16*APH + j*16, APH);
                wmma::mma_sync(oacc[j], ap, bv, oacc[j]);
            }
        }
        stg ^= 1;
    }

    __syncthreads();
    #pragma unroll
    for (int j = 0; j < 4; j++)
        wmma::store_matrix_sync(Sx + rowm*SXP + j*16, oacc[j], SXP, wmma::mem_row_major);
    __syncthreads();

    {
        const int r  = tid >> 1;
        const int c0 = (tid & 1) * 32;
        const float inv = 1.f / lrow[r];
        const float* srcr = Sx + r*SXP + c0;
        __half* dst = outp + (size_t)(b*Tn + q0 + r) * Dn + h*HDn + c0;
        #pragma unroll
        for (int j = 0; j < 32; j += 2)
            *(__half2*)(dst + j) = __floats2half2_rn(srcr[j] * inv, srcr[j+1] * inv);
    }
}

// ---------------------------------------------------------------------------
extern "C" void kernel_launch(void* const* d_in, const int* in_sizes, int n_in,
                              void* d_out, int out_size)
{
    const float* x    = (const float*)d_in[0];
    const float* Wqkv = (const float*)d_in[1];
    const float* Wo   = (const float*)d_in[2];
    const float* bo   = (const float*)d_in[3];
    float* out = (float*)d_out;

    __half *qkvh, *atth, *xh, *wqh, *woh;
    cudaGetSymbolAddress((void**)&qkvh, g_qkvh);
    cudaGetSymbolAddress((void**)&atth, g_atth);
    cudaGetSymbolAddress((void**)&xh,   g_xh);
    cudaGetSymbolAddress((void**)&wqh,  g_wqh);
    cudaGetSymbolAddress((void**)&woh,  g_woh);

    cudaFuncSetAttribute((const void*)gemm_h<1,0>,
                         cudaFuncAttributeMaxDynamicSharedMemorySize, GEMM_SMEM);
    cudaFuncSetAttribute((const void*)gemm_h<0,1>,
                         cudaFuncAttributeMaxDynamicSharedMemorySize, GEMM_SMEM);
    cudaFuncSetAttribute(attn_h_kernel,
                         cudaFuncAttributeMaxDynamicSharedMemorySize, ATT_SMEM);

    // 0) fp16 conversions of inputs
    {
        int n4;
        n4 = MROWS*Dn/4;  f2h_kernel<<<(n4+255)/256, 256>>>(x,    xh,  n4);
        n4 = Dn*QKVN/4;   f2h_kernel<<<(n4+255)/256, 256>>>(Wqkv, wqh, n4);
        n4 = Dn*Dn/4;     f2h_kernel<<<(n4+255)/256, 256>>>(Wo,   woh, n4);
    }
    // 1) qkvh(fp16) = xh @ wqh   (fp32 accum, half epilogue)
    {
        dim3 grid(QKVN/128, MROWS/128);
        gemm_h<1,0><<<grid, 256, GEMM_SMEM>>>(xh, wqh, nullptr, qkvh, nullptr,
                                              MROWS, QKVN, Dn);
    }
    // 2) RoPE + L2 norm in place on fp16 q,k (q prescaled)
    {
        int warps = Bn*Tn*Hn*2;
        rope_norm_kernel<<<warps/8, 256>>>(qkvh);
    }
    // 3) attention
    {
        dim3 grid(Bn * Hn * (Tn/128));   // 1024
        attn_h_kernel<<<grid, 256, ATT_SMEM>>>(qkvh, atth);
    }
    // 4) out(fp32) = atth @ woh + bo  (bias folded into epilogue)
    {
        dim3 grid(Dn/128, MROWS/128);
        gemm_h<0,1><<<grid, 256, GEMM_SMEM>>>(atth, woh, bo, nullptr, out,
                                              MROWS, Dn, Dn);
    }
}

// round 14
// speedup vs baseline: 4.2826x; 1.2284x over previous
#include <cuda_runtime.h>
#include <cuda_fp16.h>
#include <mma.h>
#include <math.h>
#include <stdint.h>

using namespace nvcuda;

#define Bn 4
#define Tn 2048
#define Dn 1024
#define Hn 16
#define HDn 64
#define MROWS (Bn*Tn)      // 8192
#define QKVN (3*Dn)        // 3072

__device__ __half g_qkvh[(size_t)MROWS * QKVN];
__device__ __half g_atth[(size_t)MROWS * Dn];
__device__ __half g_xh[(size_t)MROWS * Dn];
__device__ __half g_wqh[(size_t)Dn * QKVN];
__device__ __half g_woh[(size_t)Dn * Dn];

__device__ __forceinline__ uint32_t s2u(const void* p) {
    return (uint32_t)__cvta_generic_to_shared(p);
}
__device__ __forceinline__ void cp16(uint32_t dst, const void* src) {
    asm volatile("cp.async.cg.shared.global [%0], [%1], 16;" :: "r"(dst), "l"(src));
}
__device__ __forceinline__ void cp_commit() { asm volatile("cp.async.commit_group;"); }
__device__ __forceinline__ void cp_wait0()  { asm volatile("cp.async.wait_group 0;"); }

__global__ void __launch_bounds__(256) f2h_kernel(
    const float* __restrict__ src, __half* __restrict__ dst, int total4)
{
    int idx = blockIdx.x * blockDim.x + threadIdx.x;
    if (idx >= total4) return;
    float4 v = *(const float4*)&src[idx * 4];
    *(__half2*)&dst[idx*4]   = __floats2half2_rn(v.x, v.y);
    *(__half2*)&dst[idx*4+2] = __floats2half2_rn(v.z, v.w);
}

// ---------------------------------------------------------------------------
// FP16 GEMM (R13 config): 128x128 tile, BK=64, warp tile 64x32, cp.async
// double buffer; staged epilogue (OUT_HALF or fp32+bias).
// ---------------------------------------------------------------------------
#define AP_A 72
#define AP_B 136
#define A_STG (128*AP_A)
#define B_STG (64*AP_B)
#define GEMM_SMEM ((2*A_STG + 2*B_STG) * 2)
#define SP 132

template <int OUT_HALF, int WITH_BIAS>
__global__ void __launch_bounds__(256, 2) gemm_h(
    const __half* __restrict__ A, const __half* __restrict__ Bm,
    const float* __restrict__ bias,
    __half* __restrict__ Ch, float* __restrict__ Cf,
    int M, int N, int K)
{
    extern __shared__ __half smh[];
    __half* As = smh;
    __half* Bs = smh + 2*A_STG;

    const int tid = threadIdx.x;
    const int bm = blockIdx.y * 128;
    const int bn = blockIdx.x * 128;
    const int w  = tid >> 5;
    const int wm = (w >> 2) * 64;
    const int wn = (w & 3) * 32;

    wmma::fragment<wmma::accumulator, 16, 16, 16, float> acc[4][2];
    #pragma unroll
    for (int i = 0; i < 4; i++)
        #pragma unroll
        for (int j = 0; j < 2; j++) wmma::fill_fragment(acc[i][j], 0.f);

    const int nk = K / 64;

    auto prefetch = [&](int kt, int stg) {
        const int k0 = kt * 64;
        __half* ad = As + stg * A_STG;
        __half* bd = Bs + stg * B_STG;
        #pragma unroll
        for (int i = 0; i < 4; i++) {
            int id = tid + 256*i;
            int r = id >> 3, c = (id & 7) * 8;
            cp16(s2u(ad + r*AP_A + c), &A[(size_t)(bm + r) * K + k0 + c]);
        }
        #pragma unroll
        for (int i = 0; i < 4; i++) {
            int id = tid + 256*i;
            int r = id >> 4, c = (id & 15) * 8;
            cp16(s2u(bd + r*AP_B + c), &Bm[(size_t)(k0 + r) * N + bn + c]);
        }
        cp_commit();
    };

    prefetch(0, 0);
    int stg = 0;

    for (int kt = 0; kt < nk; kt++) {
        cp_wait0();
        __syncthreads();
        if (kt + 1 < nk) prefetch(kt + 1, stg ^ 1);

        const __half* a0 = As + stg * A_STG;
        const __half* b0 = Bs + stg * B_STG;
        #pragma unroll
        for (int kk = 0; kk < 4; kk++) {
            wmma::fragment<wmma::matrix_a, 16, 16, 16, __half, wmma::row_major> af[4];
            wmma::fragment<wmma::matrix_b, 16, 16, 16, __half, wmma::row_major> bf[2];
            #pragma unroll
            for (int i = 0; i < 4; i++)
                wmma::load_matrix_sync(af[i], a0 + (wm + i*16)*AP_A + kk*16, AP_A);
            #pragma unroll
            for (int j = 0; j < 2; j++)
                wmma::load_matrix_sync(bf[j], b0 + (kk*16)*AP_B + wn + j*16, AP_B);
            #pragma unroll
            for (int i = 0; i < 4; i++)
                #pragma unroll
                for (int j = 0; j < 2; j++)
                    wmma::mma_sync(acc[i][j], af[i], bf[j], acc[i][j]);
        }
        stg ^= 1;
    }

    __syncthreads();
    float* stage = reinterpret_cast<float*>(smh);
    #pragma unroll
    for (int i = 0; i < 4; i++)
        #pragma unroll
        for (int j = 0; j < 2; j++)
            wmma::store_matrix_sync(stage + (wm + i*16)*SP + wn + j*16,
                                    acc[i][j], SP, wmma::mem_row_major);
    __syncthreads();

    #pragma unroll
    for (int it = 0; it < 8; it++) {
        int idx = tid + 256*it;
        int r = idx >> 4;
        int c = (idx & 15) * 8;
        const float* srow = stage + r*SP + c;
        if (OUT_HALF) {
            __half* dst = Ch + (size_t)(bm + r) * N + bn + c;
            #pragma unroll
            for (int k = 0; k < 4; k++)
                *(__half2*)(dst + 2*k) = __floats2half2_rn(srow[2*k], srow[2*k+1]);
        } else {
            float* dst = Cf + (size_t)(bm + r) * N + bn + c;
            float4 v0 = *(const float4*)(srow);
            float4 v1 = *(const float4*)(srow + 4);
            if (WITH_BIAS) {
                const float* bp = bias + bn + c;
                v0.x += bp[0]; v0.y += bp[1]; v0.z += bp[2]; v0.w += bp[3];
                v1.x += bp[4]; v1.y += bp[5]; v1.z += bp[6]; v1.w += bp[7];
            }
            *(float4*)(dst)     = v0;
            *(float4*)(dst + 4) = v1;
        }
    }
}

// ---------------------------------------------------------------------------
// RoPE + L2 norm: fp16 in/out, in place (q pre-scaled by 1/8).
// ---------------------------------------------------------------------------
__global__ void __launch_bounds__(256) rope_norm_kernel(__half* __restrict__ qkvh)
{
    const int gw = (blockIdx.x * blockDim.x + threadIdx.x) >> 5;
    const int lane = threadIdx.x & 31;
    const int which = gw & 1;
    const int h = (gw >> 1) & (Hn - 1);
    const int t = (gw >> 5) & (Tn - 1);
    const int b = gw >> 16;

    __half* d = qkvh + (size_t)(b*Tn + t) * QKVN + which*Dn + h*HDn;

    const float inv_freq = exp2f(-(float)lane * (13.287712379549449f / 32.f));
    const float ang = (float)t * inv_freq;
    float s, c;
    sincosf(ang, &s, &c);

    const float x1 = __half2float(d[lane]);
    const float x2 = __half2float(d[lane + 32]);
    const float r1 = x1*c - x2*s;
    const float r2 = x1*s + x2*c;

    float ss = r1*r1 + r2*r2;
    #pragma unroll
    for (int off2 = 16; off2; off2 >>= 1)
        ss += __shfl_xor_sync(0xffffffffu, ss, off2);

    float inv = rsqrtf(ss + 1e-6f);
    if (which == 0) inv *= 0.125f;
    d[lane]      = __float2half(r1 * inv);
    d[lane + 32] = __float2half(r2 * inv);
}

// ---------------------------------------------------------------------------
// FP16 flash attention v4: 128 q-rows / 256 threads / 8 warps.
// S accumulated in HALF (|S|<=0.125 so precision loss ~6e-5), stored
// straight to Ph -> exp is one half2 RMW pass. No fp32 S staging buffer:
// smem 74KB -> 3 blocks/SM. Final O staged through dead K/V region.
// ---------------------------------------------------------------------------
#define APH 72
#define OXP 68                      // float pitch for O staging (in K/V region)
#define KV_STGH (64*APH)
#define SM_Q   0
#define SM_K   (SM_Q + 128*APH)
#define SM_V   (SM_K + 2*KV_STGH)
#define SM_P   (SM_V + 2*KV_STGH)
#define SM_HALVES (SM_P + 128*APH)  // 36864 halves
#define ATT_SMEM (SM_HALVES*2 + 128*4)   // + lrow

__global__ void __launch_bounds__(256) attn_h_kernel(
    const __half* __restrict__ qkvh, __half* __restrict__ outp)
{
    extern __shared__ __half smh[];
    __half* Qs = smh + SM_Q;
    __half* Ks = smh + SM_K;
    __half* Vs = smh + SM_V;
    __half* Ph = smh + SM_P;
    float* lrow = (float*)(smh + SM_HALVES);
    float* Ostage = (float*)(smh + SM_K);   // reuse K/V region after mainloop

    const int tid  = threadIdx.x;
    const int w    = tid >> 5;
    const int lane = tid & 31;

    const int qt = blockIdx.x & 15;
    const int h  = (blockIdx.x >> 4) & (Hn-1);
    const int b  = blockIdx.x >> 8;
    const int q0 = qt * 128;

    const __half* qbase = qkvh + (size_t)(b*Tn) * QKVN + h*HDn;
    const __half* kbase = qbase + Dn;
    const __half* vbase = qbase + 2*Dn;

    auto prefetch_kv = [&](int kt, int stg) {
        __half* kd = Ks + stg*KV_STGH;
        __half* vd = Vs + stg*KV_STGH;
        #pragma unroll
        for (int i = 0; i < 2; i++) {
            int id = tid + 256*i;
            int r = id >> 3, c = (id & 7) * 8;
            cp16(s2u(kd + r*APH + c), kbase + (size_t)(kt*64 + r) * QKVN + c);
        }
        #pragma unroll
        for (int i = 0; i < 2; i++) {
            int id = tid + 256*i;
            int r = id >> 3, c = (id & 7) * 8;
            cp16(s2u(vd + r*APH + c), vbase + (size_t)(kt*64 + r) * QKVN + c);
        }
        cp_commit();
    };

    #pragma unroll
    for (int i = 0; i < 4; i++) {
        int id = tid + 256*i;
        int r = id >> 3, c = (id & 7) * 8;
        cp16(s2u(Qs + r*APH + c), qbase + (size_t)(q0 + r) * QKVN + c);
    }
    cp_commit();
    prefetch_kv(0, 0);

    if (tid < 128) lrow[tid] = 0.f;

    wmma::fragment<wmma::accumulator, 16, 16, 16, float> oacc[4];
    #pragma unroll
    for (int j = 0; j < 4; j++) wmma::fill_fragment(oacc[j], 0.f);

    const int rowm = w * 16;
    int stg = 0;

    for (int kt = 0; kt < Tn/64; kt++) {
        cp_wait0();
        __syncthreads();
        if (kt + 1 < Tn/64) prefetch_kv(kt + 1, stg ^ 1);

        const __half* kc = Ks + stg*KV_STGH;
        const __half* vc = Vs + stg*KV_STGH;

        // S = Q @ K^T, HALF accumulator (safe: |S| <= 0.125)
        wmma::fragment<wmma::accumulator, 16, 16, 16, __half> sacc[4];
        #pragma unroll
        for (int j = 0; j < 4; j++) wmma::fill_fragment(sacc[j], __float2half(0.f));
        #pragma unroll
        for (int ks = 0; ks < 4; ks++) {
            wmma::fragment<wmma::matrix_a, 16, 16, 16, __half, wmma::row_major> aq;
            wmma::load_matrix_sync(aq, Qs + rowm*APH + ks*16, APH);
            #pragma unroll
            for (int j = 0; j < 4; j++) {
                wmma::fragment<wmma::matrix_b, 16, 16, 16, __half, wmma::col_major> bk;
                wmma::load_matrix_sync(bk, kc + j*16*APH + ks*16, APH);
                wmma::mma_sync(sacc[j], aq, bk, sacc[j]);
            }
        }
        #pragma unroll
        for (int j = 0; j < 4; j++)
            wmma::store_matrix_sync(Ph + rowm*APH + j*16, sacc[j], APH, wmma::mem_row_major);
        __syncwarp();

        // P = half(exp(S)) in place; row sums of rounded values.
        {
            const int rr = rowm + (lane >> 1);
            const int cc = (lane & 1) * 32;
            __half* pr = Ph + rr*APH + cc;
            float sum = 0.f;
            #pragma unroll
            for (int j = 0; j < 32; j += 2) {
                __half2 sv = *(__half2*)(pr + j);
                float e0 = __expf(__half2float(__low2half(sv)));
                float e1 = __expf(__half2float(__high2half(sv)));
                __half2 hp = __floats2half2_rn(e0, e1);
                *(__half2*)(pr + j) = hp;
                sum += __half2float(__low2half(hp)) + __half2float(__high2half(hp));
            }
            sum += __shfl_xor_sync(0xffffffffu, sum, 1);
            if (!(lane & 1)) lrow[rr] += sum;
        }
        __syncwarp();

        // O += P @ V
        #pragma unroll
        for (int ks = 0; ks < 4; ks++) {
            wmma::fragment<wmma::matrix_a, 16, 16, 16, __half, wmma::row_major> ap;
            wmma::load_matrix_sync(ap, Ph + rowm*APH + ks*16, APH);
            #pragma unroll
            for (int j = 0; j < 4; j++) {
                wmma::fragment<wmma::matrix_b, 16, 16, 16, __half, wmma::row_major> bv;
                wmma::load_matrix_sync(bv, vc + ks*16*APH + j*16, APH);
                wmma::mma_sync(oacc[j], ap, bv, oacc[j]);
            }
        }
        stg ^= 1;
    }

    // Stage O (fp32) through the dead K/V region, normalize, emit fp16.
    __syncthreads();
    #pragma unroll
    for (int j = 0; j < 4; j++)
        wmma::store_matrix_sync(Ostage + rowm*OXP + j*16, oacc[j], OXP, wmma::mem_row_major);
    __syncthreads();

    {
        const int r  = tid >> 1;
        const int c0 = (tid & 1) * 32;
        const float inv = 1.f / lrow[r];
        const float* srcr = Ostage + r*OXP + c0;
        __half* dst = outp + (size_t)(b*Tn + q0 + r) * Dn + h*HDn + c0;
        #pragma unroll
        for (int j = 0; j < 32; j += 2)
            *(__half2*)(dst + j) = __floats2half2_rn(srcr[j] * inv, srcr[j+1] * inv);
    }
}

// ---------------------------------------------------------------------------
extern "C" void kernel_launch(void* const* d_in, const int* in_sizes, int n_in,
                              void* d_out, int out_size)
{
    const float* x    = (const float*)d_in[0];
    const float* Wqkv = (const float*)d_in[1];
    const float* Wo   = (const float*)d_in[2];
    const float* bo   = (const float*)d_in[3];
    float* out = (float*)d_out;

    __half *qkvh, *atth, *xh, *wqh, *woh;
    cudaGetSymbolAddress((void**)&qkvh, g_qkvh);
    cudaGetSymbolAddress((void**)&atth, g_atth);
    cudaGetSymbolAddress((void**)&xh,   g_xh);
    cudaGetSymbolAddress((void**)&wqh,  g_wqh);
    cudaGetSymbolAddress((void**)&woh,  g_woh);

    cudaFuncSetAttribute((const void*)gemm_h<1,0>,
                         cudaFuncAttributeMaxDynamicSharedMemorySize, GEMM_SMEM);
    cudaFuncSetAttribute((const void*)gemm_h<0,1>,
                         cudaFuncAttributeMaxDynamicSharedMemorySize, GEMM_SMEM);
    cudaFuncSetAttribute(attn_h_kernel,
                         cudaFuncAttributeMaxDynamicSharedMemorySize, ATT_SMEM);

    // 0) fp16 conversions of inputs
    {
        int n4;
        n4 = MROWS*Dn/4;  f2h_kernel<<<(n4+255)/256, 256>>>(x,    xh,  n4);
        n4 = Dn*QKVN/4;   f2h_kernel<<<(n4+255)/256, 256>>>(Wqkv, wqh, n4);
        n4 = Dn*Dn/4;     f2h_kernel<<<(n4+255)/256, 256>>>(Wo,   woh, n4);
    }
    // 1) qkvh(fp16) = xh @ wqh
    {
        dim3 grid(QKVN/128, MROWS/128);
        gemm_h<1,0><<<grid, 256, GEMM_SMEM>>>(xh, wqh, nullptr, qkvh, nullptr,
                                              MROWS, QKVN, Dn);
    }
    // 2) RoPE + L2 norm in place (q prescaled)
    {
        int warps = Bn*Tn*Hn*2;
        rope_norm_kernel<<<warps/8, 256>>>(qkvh);
    }
    // 3) attention
    {
        dim3 grid(Bn * Hn * (Tn/128));   // 1024
        attn_h_kernel<<<grid, 256, ATT_SMEM>>>(qkvh, atth);
    }
    // 4) out(fp32) = atth @ woh + bo
    {
        dim3 grid(Dn/128, MROWS/128);
        gemm_h<0,1><<<grid, 256, GEMM_SMEM>>>(atth, woh, bo, nullptr, out,
                                              MROWS, Dn, Dn);
    }
}